// round 3
// baseline (speedup 1.0000x reference)
#include <cuda_runtime.h>
#include <math.h>

// ---------------- problem constants ----------------
#define N_SAMP 441000
#define ROWS   16
#define WPR    55125          // windows (of 8 samples) per row
#define TOTW   (ROWS * WPR)   // 882000
#define CHUNKS 64
#define CHUNK_W 862           // ceil(WPR / CHUNKS)
#define WARM_W 6144           // 49152-sample warmup, in windows
#define PD     10             // prefetch depth (register ring)

// exp(-1/441), exp(-1/4410) to double precision
#define A_AT_D  0.99773499530690318
#define A_REL_D 0.99977326833789451

// 20*log10(y) = C_DB * log2(y)
#define C_DB 6.0205999132796239f
// -(1 - 1/66.7) * 0.5
#define C_DN (-0.49250374812593705f)
// (1 - 0.1) * 0.5
#define C_UP 0.45f
// log2(10)/20
#define C_EXP 0.16609640474436813f

__host__ __device__ constexpr double slope_d(int m) {
    double r = 1.0;
    for (int i = 0; i < m; ++i) r *= A_AT_D;
    for (int i = m; i < 8; ++i) r *= A_REL_D;
    return r;
}

// ---------------- scratch (static device globals: allowed) ----------------
static __device__ float4 g_pa[TOTW];    // plane offsets D[0..3]
static __device__ float4 g_pb[TOTW];    // plane offsets D[4..7]
static __device__ float  g_pc[TOTW];    // plane offset  D[8]
static __device__ float  g_entry[TOTW]; // state entering each window

// ---------------- kernel 1: prepass (x -> per-window plane offsets) -------
__global__ void __launch_bounds__(256) k_prepass(const float* __restrict__ x) {
    int w = blockIdx.x * blockDim.x + threadIdx.x;
    if (w >= TOTW) return;

    const float4* x4 = (const float4*)x;
    float4 a = x4[2 * w];
    float4 b = x4[2 * w + 1];
    float v[8] = {a.x, a.y, a.z, a.w, b.x, b.y, b.z, b.w};
#pragma unroll
    for (int i = 0; i < 8; ++i)
        v[i] = C_DB * __log2f(fabsf(v[i]) + 1e-8f);

    const float AT = (float)A_AT_D, RL = (float)A_REL_D;
    const float BT = 1.0f - AT, BR = 1.0f - RL;

    // DP over attack-count m: D[m] = max offset among paths with m attacks
    float D[9];
    D[0] = BR * v[0];
    D[1] = BT * v[0];
#pragma unroll
    for (int t = 1; t < 8; ++t) {
        float bt = BT * v[t], br = BR * v[t];
        D[t + 1] = fmaf(AT, D[t], bt);          // all-attack extension
#pragma unroll
        for (int m = 7; m >= 1; --m) {          // descending: D[m-1] still old
            if (m <= t)
                D[m] = fmaxf(fmaf(AT, D[m - 1], bt), fmaf(RL, D[m], br));
        }
        D[0] = fmaf(RL, D[0], br);              // all-release
    }

    g_pa[w] = make_float4(D[0], D[1], D[2], D[3]);
    g_pb[w] = make_float4(D[4], D[5], D[6], D[7]);
    g_pc[w] = D[8];
}

// ---------------- kernel 2: chunked scan over windows ---------------------
__global__ void __launch_bounds__(32) k_scan(const float* __restrict__ x) {
    int gid = blockIdx.x * blockDim.x + threadIdx.x;   // 0..1023
    int row = gid / CHUNKS;
    int c   = gid % CHUNKS;
    int start_w = c * CHUNK_W;
    if (start_w >= WPR) return;
    int end_w  = min(start_w + CHUNK_W, WPR);
    int warm_w = max(0, start_w - WARM_W);

    float s;
    if (warm_w == 0) {
        // exact init: reference seeds the scan with rect_db[row][0]
        float x0 = x[row * N_SAMP];
        s = C_DB * __log2f(fabsf(x0) + 1e-8f);
    } else {
        s = -300.0f;   // below any reachable level; recovers via attack rate
    }

    const float4* pa = g_pa + row * WPR;
    const float4* pb = g_pb + row * WPR;
    const float*  pc = g_pc + row * WPR;
    float*        en = g_entry + row * WPR;

    const float S0 = (float)slope_d(0), S1 = (float)slope_d(1),
                S2 = (float)slope_d(2), S3 = (float)slope_d(3),
                S4 = (float)slope_d(4), S5 = (float)slope_d(5),
                S6 = (float)slope_d(6), S7 = (float)slope_d(7),
                S8 = (float)slope_d(8);

    // register ring prefetch
    float4 A[PD], B[PD];
    float  Cc[PD];
#pragma unroll
    for (int k = 0; k < PD; ++k) {
        int ix = min(warm_w + k, end_w - 1);
        A[k] = pa[ix]; B[k] = pb[ix]; Cc[k] = pc[ix];
    }

    int total = end_w - warm_w;
    int nblk  = (total + PD - 1) / PD;
    int p = warm_w;
    for (int i = 0; i < nblk; ++i) {
#pragma unroll
        for (int j = 0; j < PD; ++j) {
            float q0 = fmaf(S0, s, A[j].x);
            float q1 = fmaf(S1, s, A[j].y);
            float q2 = fmaf(S2, s, A[j].z);
            float q3 = fmaf(S3, s, A[j].w);
            float q4 = fmaf(S4, s, B[j].x);
            float q5 = fmaf(S5, s, B[j].y);
            float q6 = fmaf(S6, s, B[j].z);
            float q7 = fmaf(S7, s, B[j].w);
            float q8 = fmaf(S8, s, Cc[j]);
            float m01 = fmaxf(q0, q1), m23 = fmaxf(q2, q3);
            float m45 = fmaxf(q4, q5), m67 = fmaxf(q6, q7);
            float m03 = fmaxf(m01, m23), m47 = fmaxf(m45, m67);
            float ns  = fmaxf(fmaxf(m03, m47), q8);

            bool act = p < end_w;
            if (act && p >= start_w) en[p] = s;   // state BEFORE this window
            if (act) s = ns;

            int nx = min(p + PD, end_w - 1);      // refill ring slot j
            A[j] = pa[nx]; B[j] = pb[nx]; Cc[j] = pc[nx];
            ++p;
        }
    }
}

// ---------------- kernel 3: expand windows + compressor epilogue ----------
__global__ void __launch_bounds__(128) k_expand(const float* __restrict__ x,
                                                const float* __restrict__ thr,
                                                const float* __restrict__ dep,
                                                float* __restrict__ out) {
    int w = blockIdx.x * blockDim.x + threadIdx.x;
    if (w >= TOTW) return;
    int row = w / WPR;

    float tdb = fmaf(thr[row], 40.0f, -40.0f);   // TMIN + thr*(TMAX-TMIN)
    float dpv = dep[row];

    const float AT = (float)A_AT_D, RL = (float)A_REL_D;
    const float BT = 1.0f - AT, BR = 1.0f - RL;

    float s = g_entry[w];
    const float4* x4 = (const float4*)x;
    float4 a = x4[2 * w];
    float4 b = x4[2 * w + 1];
    float xi[8] = {a.x, a.y, a.z, a.w, b.x, b.y, b.z, b.w};
    float o[8];

#pragma unroll
    for (int i = 0; i < 8; ++i) {
        float v = C_DB * __log2f(fabsf(xi[i]) + 1e-8f);
        s = fmaxf(fmaf(AT, s, BT * v), fmaf(RL, s, BR * v));

        float dd = s - tdb;
        float gdn = 0.0f;
        if (dd > -0.1f) {
            float t = dd - 0.1f;
            gdn = C_DN * (dd + 0.1f + sqrtf(fmaf(t, t, 1e-4f)));
        }
        float du = -dd;
        float gup = 0.0f;
        if (du > -0.1f) {
            float t = du - 0.1f;
            gup = C_UP * (du + 0.1f + sqrtf(fmaf(t, t, 1e-4f)));
            gup = fminf(gup, 36.0f);
        }
        float gdb = (gdn + gup) * dpv;
        o[i] = xi[i] * exp2f(gdb * C_EXP);
    }

    float4* o4 = (float4*)out;
    o4[2 * w]     = make_float4(o[0], o[1], o[2], o[3]);
    o4[2 * w + 1] = make_float4(o[4], o[5], o[6], o[7]);
}

// ---------------- entry point ----------------
extern "C" void kernel_launch(void* const* d_in, const int* in_sizes, int n_in,
                              void* d_out, int out_size) {
    const float* x   = (const float*)d_in[0];
    const float* thr = (const float*)d_in[1];
    const float* dep = (const float*)d_in[2];
    float* out = (float*)d_out;

    k_prepass<<<(TOTW + 255) / 256, 256>>>(x);
    k_scan<<<(ROWS * CHUNKS) / 32, 32>>>(x);
    k_expand<<<(TOTW + 127) / 128, 128>>>(x, thr, dep, out);
}

// round 4
// speedup vs baseline: 1.5685x; 1.5685x over previous
#include <cuda_runtime.h>
#include <math.h>

// ---------------- problem constants ----------------
#define N_SAMP 441000
#define ROWS   16
#define WPR    55125          // 8-sample windows per row
#define TOTW   (ROWS * WPR)   // 882000
#define CHUNKS 256
#define CHUNK_W 216           // 256*216 = 55296 >= WPR ; 216 % 8 == 0
#define EPR    55128          // padded per-row stride for entry states (mult of 8)
#define WARM_W 3584           // warmup windows (28672 samples); multiple of 8
#define PD     8              // prefetch ring depth

// exp(-1/441), exp(-1/4410)
#define A_AT_D  0.99773499530690318
#define A_REL_D 0.99977326833789451
#define C_DB    6.0205999132796239f   // 20/log2(10)... (20*log10 = C_DB*log2)

__host__ __device__ constexpr double slope_d(int m) {
    double r = 1.0;
    for (int i = 0; i < m; ++i) r *= A_AT_D;
    for (int i = m; i < 8; ++i) r *= A_REL_D;
    return r;
}
#define S0F ((float)slope_d(0))
#define S1F ((float)slope_d(1))
#define S2F ((float)slope_d(2))
#define S3F ((float)slope_d(3))
#define S4F ((float)slope_d(4))
#define S5F ((float)slope_d(5))
#define S6F ((float)slope_d(6))
#define S7F ((float)slope_d(7))
#define S8F ((float)slope_d(8))

// ---------------- gain LUT config ----------------
#define LUT_N     8192
#define LUT_LO_D  (-81.0)
#define LUT_HI_D  (61.0)
#define LUT_STEP_D ((LUT_HI_D - LUT_LO_D) / (double)LUT_N)
#define LUT_LO_F   ((float)LUT_LO_D)
#define LUT_INVSTEP_F ((float)(1.0 / LUT_STEP_D))

// ---------------- scratch (static device globals) ----------------
static __device__ float4 g_pa[TOTW];       // plane offsets D[0..3]
static __device__ float4 g_pb[TOTW];       // plane offsets D[4..7]
static __device__ float  g_pc[TOTW];       // plane offset  D[8]
static __device__ float4 g_rect[2 * TOTW]; // rect_db per sample (28 MB)
static __device__ float  g_entry[ROWS * EPR];
static __device__ float2 g_lut[LUT_N];     // (m, m_next - m)

// ---------------- kernel 0: gain multiplier LUT ----------------
__device__ double lut_gain_db(double dd) {
    double gdn = 0.0;
    if (dd > -0.1) {
        double t = dd - 0.1;
        gdn = -0.49250374812593705 * (dd + 0.1 + sqrt(t * t + 1e-4));
    }
    double du = -dd;
    double gup = 0.0;
    if (du > -0.1) {
        double t = du - 0.1;
        gup = 0.45 * (du + 0.1 + sqrt(t * t + 1e-4));
        if (gup > 36.0) gup = 36.0;
    }
    return gdn + gup;
}

__global__ void k_lut() {
    int i = blockIdx.x * blockDim.x + threadIdx.x;
    if (i >= LUT_N) return;
    double d0 = LUT_LO_D + i * LUT_STEP_D;
    double m0 = pow(10.0, lut_gain_db(d0) / 20.0);
    double m1 = m0;
    if (i + 1 < LUT_N) {
        double d1 = LUT_LO_D + (i + 1) * LUT_STEP_D;
        m1 = pow(10.0, lut_gain_db(d1) / 20.0);
    }
    g_lut[i] = make_float2((float)m0, (float)(m1 - m0));
}

// ---------------- kernel 1: prepass (x -> plane offsets + rect_db) --------
__global__ void __launch_bounds__(256) k_prepass(const float* __restrict__ x) {
    int w = blockIdx.x * blockDim.x + threadIdx.x;
    if (w >= TOTW) return;

    const float4* x4 = (const float4*)x;
    float4 a = x4[2 * w];
    float4 b = x4[2 * w + 1];
    float v[8] = {a.x, a.y, a.z, a.w, b.x, b.y, b.z, b.w};
#pragma unroll
    for (int i = 0; i < 8; ++i)
        v[i] = C_DB * __log2f(fabsf(v[i]) + 1e-8f);

    g_rect[2 * w]     = make_float4(v[0], v[1], v[2], v[3]);
    g_rect[2 * w + 1] = make_float4(v[4], v[5], v[6], v[7]);

    const float AT = (float)A_AT_D, RL = (float)A_REL_D;
    const float BT = 1.0f - AT, BR = 1.0f - RL;

    // DP over attack-count m: D[m] = max offset among paths with m attacks
    float D[9];
    D[0] = BR * v[0];
    D[1] = BT * v[0];
#pragma unroll
    for (int t = 1; t < 8; ++t) {
        float bt = BT * v[t], br = BR * v[t];
        D[t + 1] = fmaf(AT, D[t], bt);
#pragma unroll
        for (int m = 7; m >= 1; --m) {
            if (m <= t)
                D[m] = fmaxf(fmaf(AT, D[m - 1], bt), fmaf(RL, D[m], br));
        }
        D[0] = fmaf(RL, D[0], br);
    }

    g_pa[w] = make_float4(D[0], D[1], D[2], D[3]);
    g_pb[w] = make_float4(D[4], D[5], D[6], D[7]);
    g_pc[w] = D[8];
}

// ---------------- kernel 2: chunked scan over windows ---------------------
#define SCAN_STEP(j)                                                          \
    {                                                                         \
        float q0 = fmaf(S0F, s, A[j].x), q1 = fmaf(S1F, s, A[j].y);           \
        float q2 = fmaf(S2F, s, A[j].z), q3 = fmaf(S3F, s, A[j].w);           \
        float q4 = fmaf(S4F, s, B[j].x), q5 = fmaf(S5F, s, B[j].y);           \
        float q6 = fmaf(S6F, s, B[j].z), q7 = fmaf(S7F, s, B[j].w);           \
        float q8 = fmaf(S8F, s, Cc[j]);                                       \
        float m01 = fmaxf(q0, q1), m23 = fmaxf(q2, q3);                       \
        float m45 = fmaxf(q4, q5), m67 = fmaxf(q6, q7);                       \
        s = fmaxf(fmaxf(fmaxf(m01, m23), fmaxf(m45, m67)), q8);               \
    }

__global__ void __launch_bounds__(32) k_scan(const float* __restrict__ x) {
    int gid = blockIdx.x * 32 + threadIdx.x;   // 0..4095
    int row = gid >> 8;                         // CHUNKS = 256
    int c   = gid & 255;
    int start_w = c * CHUNK_W;
    int end_w   = min(start_w + CHUNK_W, WPR);
    int warm_w  = max(0, start_w - WARM_W);
    int last    = end_w - 1;

    const float4* pa = g_pa + row * WPR;
    const float4* pb = g_pb + row * WPR;
    const float*  pc = g_pc + row * WPR;
    float*        en = g_entry + row * EPR;

    float s;
    if (warm_w == 0) {
        // exact init: reference seeds with rect_db[row][0]
        s = C_DB * __log2f(fabsf(x[row * N_SAMP]) + 1e-8f);
    } else {
        // level estimate: fixed point of all-attack plane, biased 25 dB low so
        // recovery runs at the fast attack rate
        const float SEST = (float)(1.0 / (1.0 - slope_d(8)));
        float e0 = pc[warm_w], e1 = pc[warm_w + 8], e2 = pc[warm_w + 16];
        s = fmaf(fmaxf(fmaxf(e0, e1), e2), SEST, -25.0f);
    }

    float4 A[PD], B[PD];
    float  Cc[PD];
#pragma unroll
    for (int k = 0; k < PD; ++k) {
        int ix = warm_w + k; if (ix > last) ix = last;
        A[k] = pa[ix]; B[k] = pb[ix]; Cc[k] = pc[ix];
    }

    int p = warm_w;
    // ---- warmup phase (no stores); length is a multiple of PD ----
    int nwb = (start_w - warm_w) >> 3;
    for (int i = 0; i < nwb; ++i) {
#pragma unroll
        for (int j = 0; j < PD; ++j) {
            SCAN_STEP(j);
            int nx = p + PD; if (nx > last) nx = last;
            A[j] = pa[nx]; B[j] = pb[nx]; Cc[j] = pc[nx];
            ++p;
        }
    }
    // ---- active phase: store entry state per window (float4-packed) ----
    int nab = (end_w - start_w + 7) >> 3;
    for (int i = 0; i < nab; ++i) {
        float ss[PD];
#pragma unroll
        for (int j = 0; j < PD; ++j) {
            ss[j] = s;                 // state BEFORE this window
            SCAN_STEP(j);
            int nx = p + PD; if (nx > last) nx = last;
            A[j] = pa[nx]; B[j] = pb[nx]; Cc[j] = pc[nx];
            ++p;
        }
        int base = p - PD;             // multiple of 8; EPR padding absorbs tail
        *(float4*)(en + base)     = make_float4(ss[0], ss[1], ss[2], ss[3]);
        *(float4*)(en + base + 4) = make_float4(ss[4], ss[5], ss[6], ss[7]);
    }
}

// ---------------- kernel 3: expand + LUT epilogue -------------------------
__global__ void __launch_bounds__(256) k_expand(const float* __restrict__ x,
                                                const float* __restrict__ thr,
                                                const float* __restrict__ dep,
                                                float* __restrict__ out) {
    int wi = blockIdx.x * 256 + threadIdx.x;
    if (wi >= WPR) return;
    int row = blockIdx.y;
    int g = row * WPR + wi;

    float tdb = fmaf(thr[row], 40.0f, -40.0f);
    float dpv = dep[row];
    bool  d1  = (dpv == 1.0f);
    float off = (-tdb - LUT_LO_F) * LUT_INVSTEP_F;

    const float AT = (float)A_AT_D, RL = (float)A_REL_D;
    const float BT = 1.0f - AT, BR = 1.0f - RL;

    float s = g_entry[row * EPR + wi];

    const float4* x4 = (const float4*)x;
    float4 xa = x4[2 * g], xb = x4[2 * g + 1];
    float4 va = g_rect[2 * g], vb = g_rect[2 * g + 1];
    float xi[8] = {xa.x, xa.y, xa.z, xa.w, xb.x, xb.y, xb.z, xb.w};
    float vv[8] = {va.x, va.y, va.z, va.w, vb.x, vb.y, vb.z, vb.w};
    float o[8];

#pragma unroll
    for (int i = 0; i < 8; ++i) {
        float v = vv[i];
        s = fmaxf(fmaf(AT, s, BT * v), fmaf(RL, s, BR * v));

        float fi = fmaf(s, LUT_INVSTEP_F, off);
        fi = fminf(fmaxf(fi, 0.0f), (float)(LUT_N - 2) + 0.999f);
        int   ii = (int)fi;
        float fr = fi - (float)ii;
        float2 e = g_lut[ii];
        float m = fmaf(fr, e.y, e.x);
        if (!d1) m = exp2f(__log2f(m) * dpv);   // uniform per-row fallback
        o[i] = xi[i] * m;
    }

    float4* o4 = (float4*)out;
    o4[2 * g]     = make_float4(o[0], o[1], o[2], o[3]);
    o4[2 * g + 1] = make_float4(o[4], o[5], o[6], o[7]);
}

// ---------------- entry point ----------------
extern "C" void kernel_launch(void* const* d_in, const int* in_sizes, int n_in,
                              void* d_out, int out_size) {
    const float* x   = (const float*)d_in[0];
    const float* thr = (const float*)d_in[1];
    const float* dep = (const float*)d_in[2];
    float* out = (float*)d_out;

    k_lut<<<LUT_N / 256, 256>>>();
    k_prepass<<<(TOTW + 255) / 256, 256>>>(x);
    k_scan<<<(ROWS * CHUNKS) / 32, 32>>>(x);
    k_expand<<<dim3((WPR + 255) / 256, ROWS), 256>>>(x, thr, dep, out);
}

// round 5
// speedup vs baseline: 4.8668x; 3.1029x over previous
#include <cuda_runtime.h>
#include <math.h>

// ---------------- problem constants ----------------
#define N_SAMP  441000
#define ROWS    16
#define WPR     55125          // 8-sample windows per row
#define TOTW    (ROWS * WPR)
#define CHUNKS  256
#define CHUNK_W 224            // 224 % 16 == 0
#define TWPR    (CHUNK_W * CHUNKS)  // 57344 transposed slots per row (incl pads)
#define EPR     55328          // per-row entry stride (max store = 246*224+224)
#define WARM_W  2240           // warmup windows; % 224 == 0, % 16 == 0
#define PD      16             // prefetch ring depth

// exp(-1/441), exp(-1/4410)
#define A_AT_D  0.99773499530690318
#define A_REL_D 0.99977326833789451
#define C_DB    6.0205999132796239f   // 20*log10(y) = C_DB * log2(y)

__host__ __device__ constexpr double slope_d(int m) {
    double r = 1.0;
    for (int i = 0; i < m; ++i) r *= A_AT_D;
    for (int i = m; i < 8; ++i) r *= A_REL_D;
    return r;
}
#define S0F ((float)slope_d(0))
#define S1F ((float)slope_d(1))
#define S2F ((float)slope_d(2))
#define S3F ((float)slope_d(3))
#define S4F ((float)slope_d(4))
#define S5F ((float)slope_d(5))
#define S6F ((float)slope_d(6))
#define S7F ((float)slope_d(7))
#define S8F ((float)slope_d(8))

// ---------------- gain LUT config ----------------
#define LUT_N         8192
#define LUT_LO_D      (-81.0)
#define LUT_HI_D      (61.0)
#define LUT_STEP_D    ((LUT_HI_D - LUT_LO_D) / (double)LUT_N)
#define LUT_LO_F      ((float)LUT_LO_D)
#define LUT_INVSTEP_F ((float)(1.0 / LUT_STEP_D))

// ---------------- scratch (static device globals, zero-initialized) -------
static __device__ float4 g_pa_t[ROWS * TWPR];  // planes D[0..3], transposed
static __device__ float4 g_pb_t[ROWS * TWPR];  // planes D[4..7], transposed
static __device__ float  g_pc_t[ROWS * TWPR];  // plane  D[8],   transposed
static __device__ float  g_entry[ROWS * EPR];  // state entering each window
static __device__ float2 g_lut[LUT_N];         // (m, m_next - m)

// ---------------- kernel 0: gain multiplier LUT ----------------
__device__ double lut_gain_db(double dd) {
    double gdn = 0.0;
    if (dd > -0.1) {
        double t = dd - 0.1;
        gdn = -0.49250374812593705 * (dd + 0.1 + sqrt(t * t + 1e-4));
    }
    double du = -dd;
    double gup = 0.0;
    if (du > -0.1) {
        double t = du - 0.1;
        gup = 0.45 * (du + 0.1 + sqrt(t * t + 1e-4));
        if (gup > 36.0) gup = 36.0;
    }
    return gdn + gup;
}

__global__ void k_lut() {
    int i = blockIdx.x * blockDim.x + threadIdx.x;
    if (i >= LUT_N) return;
    double d0 = LUT_LO_D + i * LUT_STEP_D;
    double m0 = pow(10.0, lut_gain_db(d0) / 20.0);
    double m1 = m0;
    if (i + 1 < LUT_N) {
        double d1 = LUT_LO_D + (i + 1) * LUT_STEP_D;
        m1 = pow(10.0, lut_gain_db(d1) / 20.0);
    }
    g_lut[i] = make_float2((float)m0, (float)(m1 - m0));
}

// ---------------- kernel 1: prepass (x -> transposed plane offsets) -------
// block b handles k = b (window-within-chunk), threads = q (chunk id).
// Transposed stores are perfectly coalesced; x reads are 32B-sector-exact.
__global__ void __launch_bounds__(256) k_prepass(const float* __restrict__ x) {
    int q   = threadIdx.x;          // chunk id 0..255
    int k   = blockIdx.x;           // 0..223
    int row = blockIdx.y;
    int w   = q * CHUNK_W + k;      // global window in row
    if (w >= WPR) return;

    const float4* x4 = (const float4*)(x + row * N_SAMP);
    float4 a = x4[2 * w];
    float4 b = x4[2 * w + 1];
    float v[8] = {a.x, a.y, a.z, a.w, b.x, b.y, b.z, b.w};
#pragma unroll
    for (int i = 0; i < 8; ++i)
        v[i] = C_DB * __log2f(fabsf(v[i]) + 1e-8f);

    const float AT = (float)A_AT_D, RL = (float)A_REL_D;
    const float BT = 1.0f - AT, BR = 1.0f - RL;

    // DP over attack-count m: D[m] = max offset among paths with m attacks
    float D[9];
    D[0] = BR * v[0];
    D[1] = BT * v[0];
#pragma unroll
    for (int t = 1; t < 8; ++t) {
        float bt = BT * v[t], br = BR * v[t];
        D[t + 1] = fmaf(AT, D[t], bt);
#pragma unroll
        for (int m = 7; m >= 1; --m) {
            if (m <= t)
                D[m] = fmaxf(fmaf(AT, D[m - 1], bt), fmaf(RL, D[m], br));
        }
        D[0] = fmaf(RL, D[0], br);
    }

    int idx = row * TWPR + k * CHUNKS + q;   // transposed slot
    g_pa_t[idx] = make_float4(D[0], D[1], D[2], D[3]);
    g_pb_t[idx] = make_float4(D[4], D[5], D[6], D[7]);
    g_pc_t[idx] = D[8];
}

// ---------------- kernel 2: chunked scan over windows ---------------------
#define SCAN_STEP(j)                                                          \
    {                                                                         \
        float q0 = fmaf(S0F, s, A[j].x), q1 = fmaf(S1F, s, A[j].y);           \
        float q2 = fmaf(S2F, s, A[j].z), q3 = fmaf(S3F, s, A[j].w);           \
        float q4 = fmaf(S4F, s, B[j].x), q5 = fmaf(S5F, s, B[j].y);           \
        float q6 = fmaf(S6F, s, B[j].z), q7 = fmaf(S7F, s, B[j].w);           \
        float q8 = fmaf(S8F, s, Cc[j]);                                       \
        float m01 = fmaxf(q0, q1), m23 = fmaxf(q2, q3);                       \
        float m45 = fmaxf(q4, q5), m67 = fmaxf(q6, q7);                       \
        s = fmaxf(fmaxf(fmaxf(m01, m23), fmaxf(m45, m67)), q8);               \
    }

#define RING_ADVANCE()                                                        \
    {                                                                         \
        fk += PD;                                                             \
        if (fk == CHUNK_W) {                                                  \
            fk = 0; ++fq;                                                     \
            paf = pa + fq; pbf = pb + fq; pcf = pc + fq;                      \
        } else {                                                              \
            paf += PD * CHUNKS; pbf += PD * CHUNKS; pcf += PD * CHUNKS;       \
        }                                                                     \
    }

__global__ void __launch_bounds__(32) k_scan(const float* __restrict__ x) {
    int gid = blockIdx.x * 32 + threadIdx.x;   // 0..4095
    int row = gid >> 8;
    int c   = gid & 255;
    int start_w = c * CHUNK_W;
    if (start_w >= WPR) return;
    int warm_w = max(0, start_w - WARM_W);     // always % 224 == 0 -> k0 = 0

    const float4* pa = g_pa_t + row * TWPR;
    const float4* pb = g_pb_t + row * TWPR;
    const float*  pc = g_pc_t + row * TWPR;

    int fq = warm_w / CHUNK_W;
    int fk = 0;
    const float4* paf = pa + fq;
    const float4* pbf = pb + fq;
    const float*  pcf = pc + fq;

    float4 A[PD], B[PD];
    float  Cc[PD];
#pragma unroll
    for (int j = 0; j < PD; ++j) {
        A[j]  = paf[j * CHUNKS];
        B[j]  = pbf[j * CHUNKS];
        Cc[j] = pcf[j * CHUNKS];
    }
    RING_ADVANCE();

    float s;
    if (warm_w == 0) {
        // exact init: reference seeds with rect_db[row][0]
        s = C_DB * __log2f(fabsf(x[row * N_SAMP]) + 1e-8f);
    } else {
        // seed: fixed point of all-attack plane, biased 25 dB low so
        // recovery runs at the fast attack rate
        const float SEST = (float)(1.0 / (1.0 - slope_d(8)));
        s = fmaf(Cc[0], SEST, -25.0f);
    }

    // ---- warmup (no stores) ----
    int nwb = (start_w - warm_w) >> 4;         // whole 16-blocks for ALL lanes
    for (int i = 0; i < nwb; ++i) {
#pragma unroll
        for (int j = 0; j < PD; ++j) {
            SCAN_STEP(j);
            A[j]  = paf[j * CHUNKS];
            B[j]  = pbf[j * CHUNKS];
            Cc[j] = pcf[j * CHUNKS];
        }
        RING_ADVANCE();
    }

    // ---- active: 14 blocks of 16 windows, store entry states ----
    float* en = g_entry + row * EPR + start_w;
    for (int i = 0; i < CHUNK_W / PD; ++i) {
        float ss[PD];
#pragma unroll
        for (int j = 0; j < PD; ++j) {
            ss[j] = s;                          // state BEFORE this window
            SCAN_STEP(j);
            A[j]  = paf[j * CHUNKS];
            B[j]  = pbf[j * CHUNKS];
            Cc[j] = pcf[j * CHUNKS];
        }
        RING_ADVANCE();
        float4* e4 = (float4*)(en + i * PD);
        e4[0] = make_float4(ss[0],  ss[1],  ss[2],  ss[3]);
        e4[1] = make_float4(ss[4],  ss[5],  ss[6],  ss[7]);
        e4[2] = make_float4(ss[8],  ss[9],  ss[10], ss[11]);
        e4[3] = make_float4(ss[12], ss[13], ss[14], ss[15]);
    }
}

// ---------------- kernel 3: expand + LUT epilogue -------------------------
__global__ void __launch_bounds__(256) k_expand(const float* __restrict__ x,
                                                const float* __restrict__ thr,
                                                const float* __restrict__ dep,
                                                float* __restrict__ out) {
    int wi = blockIdx.x * 256 + threadIdx.x;
    if (wi >= WPR) return;
    int row = blockIdx.y;
    long g = (long)row * WPR + wi;

    float tdb = fmaf(thr[row], 40.0f, -40.0f);
    float dpv = dep[row];
    bool  d1  = (dpv == 1.0f);
    float off = (-tdb - LUT_LO_F) * LUT_INVSTEP_F;

    const float AT = (float)A_AT_D, RL = (float)A_REL_D;
    const float BT = 1.0f - AT, BR = 1.0f - RL;

    float s = g_entry[row * EPR + wi];

    const float4* x4 = (const float4*)x;
    float4 xa = x4[2 * g], xb = x4[2 * g + 1];
    float xi[8] = {xa.x, xa.y, xa.z, xa.w, xb.x, xb.y, xb.z, xb.w};
    float o[8];

#pragma unroll
    for (int i = 0; i < 8; ++i) {
        float v = C_DB * __log2f(fabsf(xi[i]) + 1e-8f);
        s = fmaxf(fmaf(AT, s, BT * v), fmaf(RL, s, BR * v));

        float fi = fmaf(s, LUT_INVSTEP_F, off);
        fi = fminf(fmaxf(fi, 0.0f), (float)(LUT_N - 2) + 0.999f);
        int   ii = (int)fi;
        float fr = fi - (float)ii;
        float2 e = g_lut[ii];
        float m = fmaf(fr, e.y, e.x);
        if (!d1) m = exp2f(__log2f(m) * dpv);   // uniform per-row fallback
        o[i] = xi[i] * m;
    }

    float4* o4 = (float4*)out;
    o4[2 * g]     = make_float4(o[0], o[1], o[2], o[3]);
    o4[2 * g + 1] = make_float4(o[4], o[5], o[6], o[7]);
}

// ---------------- entry point ----------------
extern "C" void kernel_launch(void* const* d_in, const int* in_sizes, int n_in,
                              void* d_out, int out_size) {
    const float* x   = (const float*)d_in[0];
    const float* thr = (const float*)d_in[1];
    const float* dep = (const float*)d_in[2];
    float* out = (float*)d_out;

    k_lut<<<LUT_N / 256, 256>>>();
    k_prepass<<<dim3(CHUNK_W, ROWS), 256>>>(x);
    k_scan<<<(ROWS * CHUNKS) / 32, 32>>>(x);
    k_expand<<<dim3((WPR + 255) / 256, ROWS), 256>>>(x, thr, dep, out);
}

// round 6
// speedup vs baseline: 7.0139x; 1.4412x over previous
#include <cuda_runtime.h>
#include <math.h>

// ---------------- problem constants ----------------
#define N_SAMP  441000
#define ROWS    16
#define WPR16   27563          // ceil(441000/16); last window has 8 valid samples
#define FULLW   27562          // windows with all 16 samples valid
#define CHUNKS  256
#define CW      112            // 16-sample windows per chunk; 112 % 8 == 0
#define TWPR    (CW * CHUNKS)  // 28672 transposed slots per row
#define EPR     28672          // per-row entry stride
#define WARM_W  672            // warmup windows = 10752 samples; 672 % 112 == 0
#define PD      8              // prefetch ring depth

// exp(-1/441), exp(-1/4410)
#define A_AT_D  0.99773499530690318
#define A_REL_D 0.99977326833789451
#define C_DB    6.0205999132796239f   // 20*log10(y) = C_DB * log2(y)

__host__ __device__ constexpr double slope16(int m) {
    double r = 1.0;
    for (int i = 0; i < m; ++i) r *= A_AT_D;
    for (int i = m; i < 16; ++i) r *= A_REL_D;
    return r;
}
#define SC(m) ((float)slope16(m))

// ---------------- gain LUT config ----------------
#define LUT_N         8192
#define LUT_LO_D      (-81.0)
#define LUT_HI_D      (61.0)
#define LUT_STEP_D    ((LUT_HI_D - LUT_LO_D) / (double)LUT_N)
#define LUT_LO_F      ((float)LUT_LO_D)
#define LUT_INVSTEP_F ((float)(1.0 / LUT_STEP_D))

// ---------------- scratch (static device globals) ----------------
static __device__ float4 g_p0[ROWS * TWPR];   // planes D[0..3]   (transposed)
static __device__ float4 g_p1[ROWS * TWPR];   // planes D[4..7]
static __device__ float4 g_p2[ROWS * TWPR];   // planes D[8..11]
static __device__ float4 g_p3[ROWS * TWPR];   // planes D[12..15]
static __device__ float  g_p4[ROWS * TWPR];   // plane  D[16]
static __device__ float  g_entry[ROWS * EPR]; // state entering each window
static __device__ float2 g_lut[LUT_N];        // (m, m_next - m)

// ---------------- LUT builder (device fn, called from prepass blocks) -----
__device__ double lut_gain_db(double dd) {
    double gdn = 0.0;
    if (dd > -0.1) {
        double t = dd - 0.1;
        gdn = -0.49250374812593705 * (dd + 0.1 + sqrt(t * t + 1e-4));
    }
    double du = -dd;
    double gup = 0.0;
    if (du > -0.1) {
        double t = du - 0.1;
        gup = 0.45 * (du + 0.1 + sqrt(t * t + 1e-4));
        if (gup > 36.0) gup = 36.0;
    }
    return gdn + gup;
}

// ---------------- kernel 1: prepass (x -> 17 transposed planes) -----------
// grid (CW, ROWS), block 256. thread q = chunk id, block.x = k within chunk.
__global__ void __launch_bounds__(256) k_prepass(const float* __restrict__ x) {
    int q   = threadIdx.x;
    int k   = blockIdx.x;
    int row = blockIdx.y;

    // fold LUT build into the first 32 blocks of row 0
    if (row == 0 && k < LUT_N / 256) {
        int i = k * 256 + q;
        double d0 = LUT_LO_D + i * LUT_STEP_D;
        double m0 = pow(10.0, lut_gain_db(d0) / 20.0);
        double m1 = m0;
        if (i + 1 < LUT_N) {
            double d1 = LUT_LO_D + (i + 1) * LUT_STEP_D;
            m1 = pow(10.0, lut_gain_db(d1) / 20.0);
        }
        g_lut[i] = make_float2((float)m0, (float)(m1 - m0));
    }

    int w = q * CW + k;                 // global 16-window index in row
    const float* xr = x + row * N_SAMP;
    float v[16];
    if (w < FULLW) {
        const float4* x4 = (const float4*)(xr + w * 16);
        float4 a = x4[0], b = x4[1], c = x4[2], d = x4[3];
        v[0]=a.x; v[1]=a.y; v[2]=a.z; v[3]=a.w;
        v[4]=b.x; v[5]=b.y; v[6]=b.z; v[7]=b.w;
        v[8]=c.x; v[9]=c.y; v[10]=c.z; v[11]=c.w;
        v[12]=d.x; v[13]=d.y; v[14]=d.z; v[15]=d.w;
    } else {
        int base = w * 16;
#pragma unroll
        for (int i = 0; i < 16; ++i)
            v[i] = (base + i < N_SAMP) ? xr[base + i] : 0.0f;  // 0 -> -160 dB
    }
#pragma unroll
    for (int i = 0; i < 16; ++i)
        v[i] = C_DB * __log2f(fabsf(v[i]) + 1e-8f);

    const float AT = (float)A_AT_D, RL = (float)A_REL_D;
    const float BT = 1.0f - AT, BR = 1.0f - RL;

    // DP over attack-count m: D[m] = max offset among paths with m attacks
    float D[17];
    D[0] = BR * v[0];
    D[1] = BT * v[0];
#pragma unroll
    for (int t = 1; t < 16; ++t) {
        float bt = BT * v[t], br = BR * v[t];
        D[t + 1] = fmaf(AT, D[t], bt);
#pragma unroll
        for (int m = 15; m >= 1; --m) {
            if (m <= t)
                D[m] = fmaxf(fmaf(AT, D[m - 1], bt), fmaf(RL, D[m], br));
        }
        D[0] = fmaf(RL, D[0], br);
    }

    int idx = row * TWPR + k * CHUNKS + q;   // transposed slot (coalesced)
    g_p0[idx] = make_float4(D[0],  D[1],  D[2],  D[3]);
    g_p1[idx] = make_float4(D[4],  D[5],  D[6],  D[7]);
    g_p2[idx] = make_float4(D[8],  D[9],  D[10], D[11]);
    g_p3[idx] = make_float4(D[12], D[13], D[14], D[15]);
    g_p4[idx] = D[16];
}

// ---------------- kernel 2: chunked scan over 16-windows ------------------
#define SCAN_STEP(j)                                                          \
    {                                                                         \
        float q0  = fmaf(SC(0),  s, A0[j].x), q1  = fmaf(SC(1),  s, A0[j].y); \
        float q2  = fmaf(SC(2),  s, A0[j].z), q3  = fmaf(SC(3),  s, A0[j].w); \
        float q4  = fmaf(SC(4),  s, A1[j].x), q5  = fmaf(SC(5),  s, A1[j].y); \
        float q6  = fmaf(SC(6),  s, A1[j].z), q7  = fmaf(SC(7),  s, A1[j].w); \
        float q8  = fmaf(SC(8),  s, A2[j].x), q9  = fmaf(SC(9),  s, A2[j].y); \
        float q10 = fmaf(SC(10), s, A2[j].z), q11 = fmaf(SC(11), s, A2[j].w); \
        float q12 = fmaf(SC(12), s, A3[j].x), q13 = fmaf(SC(13), s, A3[j].y); \
        float q14 = fmaf(SC(14), s, A3[j].z), q15 = fmaf(SC(15), s, A3[j].w); \
        float q16 = fmaf(SC(16), s, C4[j]);                                   \
        float a0 = fmaxf(q0, q1),   a1 = fmaxf(q2, q3);                       \
        float a2 = fmaxf(q4, q5),   a3 = fmaxf(q6, q7);                       \
        float a4 = fmaxf(q8, q9),   a5 = fmaxf(q10, q11);                     \
        float a6 = fmaxf(q12, q13), a7 = fmaxf(q14, q15);                     \
        float b0 = fmaxf(a0, a1), b1 = fmaxf(a2, a3);                         \
        float b2 = fmaxf(a4, a5), b3 = fmaxf(a6, a7);                         \
        float c0 = fmaxf(b0, b1), c1 = fmaxf(b2, b3);                         \
        s = fmaxf(fmaxf(c0, c1), q16);                                        \
    }

#define RING_REFILL(j)                                                        \
    {                                                                         \
        A0[j] = pf0[(j) * CHUNKS]; A1[j] = pf1[(j) * CHUNKS];                 \
        A2[j] = pf2[(j) * CHUNKS]; A3[j] = pf3[(j) * CHUNKS];                 \
        C4[j] = pf4[(j) * CHUNKS];                                            \
    }

#define RING_ADVANCE()                                                        \
    {                                                                         \
        fk += PD;                                                             \
        if (fk == CW) {                                                       \
            fk = 0; ++fq;                                                     \
            pf0 = b0p + fq; pf1 = b1p + fq; pf2 = b2p + fq;                   \
            pf3 = b3p + fq; pf4 = b4p + fq;                                   \
        } else {                                                              \
            pf0 += PD * CHUNKS; pf1 += PD * CHUNKS; pf2 += PD * CHUNKS;       \
            pf3 += PD * CHUNKS; pf4 += PD * CHUNKS;                           \
        }                                                                     \
    }

__global__ void __launch_bounds__(32) k_scan(const float* __restrict__ x) {
    int gid = blockIdx.x * 32 + threadIdx.x;   // 0..4095
    int row = gid >> 8;
    int c   = gid & 255;
    int start_w = c * CW;
    int warm_w  = max(0, start_w - WARM_W);    // multiple of CW

    const float4* b0p = g_p0 + row * TWPR;
    const float4* b1p = g_p1 + row * TWPR;
    const float4* b2p = g_p2 + row * TWPR;
    const float4* b3p = g_p3 + row * TWPR;
    const float*  b4p = g_p4 + row * TWPR;

    int fq = warm_w / CW;
    int fk = 0;
    const float4* pf0 = b0p + fq;
    const float4* pf1 = b1p + fq;
    const float4* pf2 = b2p + fq;
    const float4* pf3 = b3p + fq;
    const float*  pf4 = b4p + fq;

    float4 A0[PD], A1[PD], A2[PD], A3[PD];
    float  C4[PD];
#pragma unroll
    for (int j = 0; j < PD; ++j) RING_REFILL(j);
    RING_ADVANCE();

    float s;
    if (warm_w == 0) {
        // exact init: reference seeds with rect_db[row][0]
        s = C_DB * __log2f(fabsf(x[row * N_SAMP]) + 1e-8f);
    } else {
        // seed: fixed point of the all-attack plane, biased 25 dB low so
        // recovery runs at the fast attack rate
        const float SEST = (float)(1.0 / (1.0 - slope16(16)));
        s = fmaf(C4[0], SEST, -25.0f);
    }

    // ---- warmup (no stores) ----
    int nwb = (start_w - warm_w) >> 3;          // blocks of PD=8
    for (int i = 0; i < nwb; ++i) {
#pragma unroll
        for (int j = 0; j < PD; ++j) {
            SCAN_STEP(j);
            RING_REFILL(j);
        }
        RING_ADVANCE();
    }

    // ---- active: CW/PD = 14 blocks, store entry states ----
    float* en = g_entry + row * EPR + start_w;
    for (int i = 0; i < CW / PD; ++i) {
        float ss[PD];
#pragma unroll
        for (int j = 0; j < PD; ++j) {
            ss[j] = s;                          // state BEFORE this window
            SCAN_STEP(j);
            RING_REFILL(j);
        }
        RING_ADVANCE();
        float4* e4 = (float4*)(en + i * PD);
        e4[0] = make_float4(ss[0], ss[1], ss[2], ss[3]);
        e4[1] = make_float4(ss[4], ss[5], ss[6], ss[7]);
    }
}

// ---------------- kernel 3: expand + LUT epilogue -------------------------
__global__ void __launch_bounds__(256) k_expand(const float* __restrict__ x,
                                                const float* __restrict__ thr,
                                                const float* __restrict__ dep,
                                                float* __restrict__ out) {
    int wi = blockIdx.x * 256 + threadIdx.x;
    if (wi >= WPR16) return;
    int row = blockIdx.y;

    float tdb = fmaf(thr[row], 40.0f, -40.0f);
    float dpv = dep[row];
    bool  d1  = (dpv == 1.0f);
    float off = (-tdb - LUT_LO_F) * LUT_INVSTEP_F;

    const float AT = (float)A_AT_D, RL = (float)A_REL_D;
    const float BT = 1.0f - AT, BR = 1.0f - RL;

    float s = g_entry[row * EPR + wi];

    const float* xr = x + row * N_SAMP;
    float* outr = out + row * N_SAMP;
    int base = wi * 16;
    int nval = (wi < FULLW) ? 16 : (N_SAMP - base);   // 16 or 8

    float xi[16];
    if (nval == 16) {
        const float4* x4 = (const float4*)(xr + base);
        float4 a = x4[0], b = x4[1], c = x4[2], d = x4[3];
        xi[0]=a.x; xi[1]=a.y; xi[2]=a.z; xi[3]=a.w;
        xi[4]=b.x; xi[5]=b.y; xi[6]=b.z; xi[7]=b.w;
        xi[8]=c.x; xi[9]=c.y; xi[10]=c.z; xi[11]=c.w;
        xi[12]=d.x; xi[13]=d.y; xi[14]=d.z; xi[15]=d.w;
    } else {
#pragma unroll
        for (int i = 0; i < 16; ++i)
            xi[i] = (i < nval) ? xr[base + i] : 0.0f;
    }

    float o[16];
#pragma unroll
    for (int i = 0; i < 16; ++i) {
        float v = C_DB * __log2f(fabsf(xi[i]) + 1e-8f);
        s = fmaxf(fmaf(AT, s, BT * v), fmaf(RL, s, BR * v));

        float fi = fmaf(s, LUT_INVSTEP_F, off);
        fi = fminf(fmaxf(fi, 0.0f), (float)(LUT_N - 2) + 0.999f);
        int   ii = (int)fi;
        float fr = fi - (float)ii;
        float2 e = g_lut[ii];
        float m = fmaf(fr, e.y, e.x);
        if (!d1) m = exp2f(__log2f(m) * dpv);   // uniform per-row fallback
        o[i] = xi[i] * m;
    }

    if (nval == 16) {
        float4* o4 = (float4*)(outr + base);
        o4[0] = make_float4(o[0],  o[1],  o[2],  o[3]);
        o4[1] = make_float4(o[4],  o[5],  o[6],  o[7]);
        o4[2] = make_float4(o[8],  o[9],  o[10], o[11]);
        o4[3] = make_float4(o[12], o[13], o[14], o[15]);
    } else {
#pragma unroll
        for (int i = 0; i < 16; ++i)
            if (i < nval) outr[base + i] = o[i];
    }
}

// ---------------- entry point ----------------
extern "C" void kernel_launch(void* const* d_in, const int* in_sizes, int n_in,
                              void* d_out, int out_size) {
    const float* x   = (const float*)d_in[0];
    const float* thr = (const float*)d_in[1];
    const float* dep = (const float*)d_in[2];
    float* out = (float*)d_out;

    k_prepass<<<dim3(CW, ROWS), 256>>>(x);
    k_scan<<<(ROWS * CHUNKS) / 32, 32>>>(x);
    k_expand<<<dim3((WPR16 + 255) / 256, ROWS), 256>>>(x, thr, dep, out);
}

// round 7
// speedup vs baseline: 7.0542x; 1.0058x over previous
#include <cuda_runtime.h>
#include <math.h>

// ---------------- problem constants ----------------
#define N_SAMP  441000
#define ROWS    16
#define WPR16   27563          // ceil(441000/16); last window has 8 valid samples
#define FULLW   27562
#define CHUNKS  320
#define CW      88             // windows per chunk; 88 % 8 == 0
#define TWPR    (CW * CHUNKS)  // 28160 transposed slots per row
#define EPR     TWPR
#define WARM_W  616            // warmup windows = 9856 samples; 616 % 88 == 0
#define PD      8

// exp(-1/441), exp(-1/4410)
#define A_AT_D  0.99773499530690318
#define A_REL_D 0.99977326833789451
#define C_DB    6.0205999132796239f   // 20*log10(y) = C_DB * log2(y)

__host__ __device__ constexpr double slope16(int m) {
    double r = 1.0;
    for (int i = 0; i < m; ++i) r *= A_AT_D;
    for (int i = m; i < 16; ++i) r *= A_REL_D;
    return r;
}
#define SC(m) ((float)slope16(m))

// ---------------- gain LUT config ----------------
#define LUT_N         8192
#define LUT_LO_D      (-81.0)
#define LUT_HI_D      (61.0)
#define LUT_STEP_D    ((LUT_HI_D - LUT_LO_D) / (double)LUT_N)
#define LUT_LO_F      ((float)LUT_LO_D)
#define LUT_INVSTEP_F ((float)(1.0 / LUT_STEP_D))

// ---------------- packed f32x2 helpers ----------------
#define FFMA2_(d, a, b, c) \
    asm("fma.rn.f32x2 %0, %1, %2, %3;" : "=l"(d) : "l"(a), "l"(b), "l"(c))
#define PACKF2(d, lo, hi) \
    asm("mov.b64 %0, {%1, %2};" : "=l"(d) : "f"(lo), "f"(hi))
#define UNPACKF2(lo, hi, d) \
    asm("mov.b64 {%0, %1}, %2;" : "=f"(lo), "=f"(hi) : "l"(d))

// ---------------- scratch (static device globals) ----------------
static __device__ float4 g_p0[ROWS * TWPR];   // planes D[0..3]   (transposed)
static __device__ float4 g_p1[ROWS * TWPR];   // planes D[4..7]
static __device__ float4 g_p2[ROWS * TWPR];   // planes D[8..11]
static __device__ float4 g_p3[ROWS * TWPR];   // planes D[12..15]
static __device__ float  g_p4[ROWS * TWPR];   // plane D[16], grouped 4-per-f4
static __device__ float  g_entry[ROWS * EPR];
static __device__ float2 g_lut[LUT_N];        // (m, m_next - m)

// ---------------- LUT builder ----------------
__device__ double lut_gain_db(double dd) {
    double gdn = 0.0;
    if (dd > -0.1) {
        double t = dd - 0.1;
        gdn = -0.49250374812593705 * (dd + 0.1 + sqrt(t * t + 1e-4));
    }
    double du = -dd;
    double gup = 0.0;
    if (du > -0.1) {
        double t = du - 0.1;
        gup = 0.45 * (du + 0.1 + sqrt(t * t + 1e-4));
        if (gup > 36.0) gup = 36.0;
    }
    return gdn + gup;
}

// ---------------- kernel 1: prepass (x -> 17 transposed planes) -----------
// grid (CW, ROWS), block CHUNKS. thread q = chunk id, block.x = k in chunk.
__global__ void __launch_bounds__(CHUNKS) k_prepass(const float* __restrict__ x) {
    int q   = threadIdx.x;          // 0..319
    int k   = blockIdx.x;           // 0..87
    int row = blockIdx.y;

    if (row == 0 && k < 26) {       // fold LUT build in
        int i = k * CHUNKS + q;
        if (i < LUT_N) {
            double d0 = LUT_LO_D + i * LUT_STEP_D;
            double m0 = pow(10.0, lut_gain_db(d0) / 20.0);
            double m1 = m0;
            if (i + 1 < LUT_N) {
                double d1 = LUT_LO_D + (i + 1) * LUT_STEP_D;
                m1 = pow(10.0, lut_gain_db(d1) / 20.0);
            }
            g_lut[i] = make_float2((float)m0, (float)(m1 - m0));
        }
    }

    int w = q * CW + k;             // global 16-window index in row
    const float* xr = x + row * N_SAMP;
    float v[16];
    if (w < FULLW) {
        const float4* x4 = (const float4*)(xr + w * 16);
        float4 a = x4[0], b = x4[1], c = x4[2], d = x4[3];
        v[0]=a.x; v[1]=a.y; v[2]=a.z; v[3]=a.w;
        v[4]=b.x; v[5]=b.y; v[6]=b.z; v[7]=b.w;
        v[8]=c.x; v[9]=c.y; v[10]=c.z; v[11]=c.w;
        v[12]=d.x; v[13]=d.y; v[14]=d.z; v[15]=d.w;
    } else {
        int base = w * 16;
#pragma unroll
        for (int i = 0; i < 16; ++i)
            v[i] = (base + i < N_SAMP) ? xr[base + i] : 0.0f;
    }
#pragma unroll
    for (int i = 0; i < 16; ++i)
        v[i] = C_DB * __log2f(fabsf(v[i]) + 1e-8f);

    const float AT = (float)A_AT_D, RL = (float)A_REL_D;
    const float BT = 1.0f - AT, BR = 1.0f - RL;

    float D[17];
    D[0] = BR * v[0];
    D[1] = BT * v[0];
#pragma unroll
    for (int t = 1; t < 16; ++t) {
        float bt = BT * v[t], br = BR * v[t];
        D[t + 1] = fmaf(AT, D[t], bt);
#pragma unroll
        for (int m = 15; m >= 1; --m) {
            if (m <= t)
                D[m] = fmaxf(fmaf(AT, D[m - 1], bt), fmaf(RL, D[m], br));
        }
        D[0] = fmaf(RL, D[0], br);
    }

    int idx = row * TWPR + k * CHUNKS + q;   // transposed slot (coalesced)
    g_p0[idx] = make_float4(D[0],  D[1],  D[2],  D[3]);
    g_p1[idx] = make_float4(D[4],  D[5],  D[6],  D[7]);
    g_p2[idx] = make_float4(D[8],  D[9],  D[10], D[11]);
    g_p3[idx] = make_float4(D[12], D[13], D[14], D[15]);
    // D[16] grouped: 4 consecutive k per float4 slot
    g_p4[row * TWPR + ((k >> 2) * CHUNKS + q) * 4 + (k & 3)] = D[16];
}

// ---------------- kernel 2: chunked scan ----------------
#define STEP(j, c4v)                                                          \
    {                                                                         \
        unsigned long long s2, r0, r1, r2, r3, r4, r5, r6, r7;                \
        PACKF2(s2, s, s);                                                     \
        FFMA2_(r0, s2, K01, U0[j].x); FFMA2_(r1, s2, K23, U0[j].y);           \
        FFMA2_(r2, s2, K45, U1[j].x); FFMA2_(r3, s2, K67, U1[j].y);           \
        FFMA2_(r4, s2, K89, U2[j].x); FFMA2_(r5, s2, KAB, U2[j].y);           \
        FFMA2_(r6, s2, KCD, U3[j].x); FFMA2_(r7, s2, KEF, U3[j].y);           \
        float q16 = fmaf(SC(16), s, c4v);                                     \
        float e0, e1, t0, t1, t2, t3, t4, t5, t6, t7;                         \
        UNPACKF2(e0, e1, r0); t0 = fmaxf(e0, e1);                             \
        UNPACKF2(e0, e1, r1); t1 = fmaxf(e0, e1);                             \
        UNPACKF2(e0, e1, r2); t2 = fmaxf(e0, e1);                             \
        UNPACKF2(e0, e1, r3); t3 = fmaxf(e0, e1);                             \
        UNPACKF2(e0, e1, r4); t4 = fmaxf(e0, e1);                             \
        UNPACKF2(e0, e1, r5); t5 = fmaxf(e0, e1);                             \
        UNPACKF2(e0, e1, r6); t6 = fmaxf(e0, e1);                             \
        UNPACKF2(e0, e1, r7); t7 = fmaxf(e0, e1);                             \
        float u0 = fmaxf(t0, t1), u1 = fmaxf(t2, t3);                         \
        float u2 = fmaxf(t4, t5), u3 = fmaxf(t6, t7);                         \
        s = fmaxf(fmaxf(fmaxf(u0, u1), fmaxf(u2, u3)), q16);                  \
    }

#define REFILL(j)                                                             \
    {                                                                         \
        U0[j] = pf0[(j) * CHUNKS]; U1[j] = pf1[(j) * CHUNKS];                 \
        U2[j] = pf2[(j) * CHUNKS]; U3[j] = pf3[(j) * CHUNKS];                 \
    }

#define ADVANCE()                                                             \
    {                                                                         \
        fk += PD;                                                             \
        if (fk == CW) {                                                       \
            fk = 0; ++fq;                                                     \
            pf0 = b0 + fq; pf1 = b1 + fq; pf2 = b2 + fq; pf3 = b3 + fq;       \
            pf4 = b4 + fq;                                                    \
        } else {                                                              \
            pf0 += PD * CHUNKS; pf1 += PD * CHUNKS;                           \
            pf2 += PD * CHUNKS; pf3 += PD * CHUNKS;                           \
            pf4 += 2 * CHUNKS;                                                \
        }                                                                     \
    }

#define BLOCK8()                                                              \
    {                                                                         \
        STEP(0, CCa.x); REFILL(0); STEP(1, CCa.y); REFILL(1);                 \
        STEP(2, CCa.z); REFILL(2); STEP(3, CCa.w); REFILL(3);                 \
        CCa = pf4[0];                                                         \
        STEP(4, CCb.x); REFILL(4); STEP(5, CCb.y); REFILL(5);                 \
        STEP(6, CCb.z); REFILL(6); STEP(7, CCb.w); REFILL(7);                 \
        CCb = pf4[CHUNKS];                                                    \
        ADVANCE();                                                            \
    }

__global__ void __launch_bounds__(32) k_scan(const float* __restrict__ x) {
    int gid = blockIdx.x * 32 + threadIdx.x;   // 0..5119
    int row = gid / CHUNKS;
    int c   = gid % CHUNKS;
    int start_w = c * CW;
    int warm_w  = max(0, start_w - WARM_W);    // multiple of CW

    const ulonglong2* b0 = (const ulonglong2*)(g_p0 + row * TWPR);
    const ulonglong2* b1 = (const ulonglong2*)(g_p1 + row * TWPR);
    const ulonglong2* b2 = (const ulonglong2*)(g_p2 + row * TWPR);
    const ulonglong2* b3 = (const ulonglong2*)(g_p3 + row * TWPR);
    const float4*     b4 = (const float4*)g_p4 + row * (TWPR / 4);

    int fq = warm_w / CW;
    int fk = 0;
    const ulonglong2* pf0 = b0 + fq;
    const ulonglong2* pf1 = b1 + fq;
    const ulonglong2* pf2 = b2 + fq;
    const ulonglong2* pf3 = b3 + fq;
    const float4*     pf4 = b4 + fq;

    unsigned long long K01, K23, K45, K67, K89, KAB, KCD, KEF;
    PACKF2(K01, SC(0),  SC(1));  PACKF2(K23, SC(2),  SC(3));
    PACKF2(K45, SC(4),  SC(5));  PACKF2(K67, SC(6),  SC(7));
    PACKF2(K89, SC(8),  SC(9));  PACKF2(KAB, SC(10), SC(11));
    PACKF2(KCD, SC(12), SC(13)); PACKF2(KEF, SC(14), SC(15));

    ulonglong2 U0[PD], U1[PD], U2[PD], U3[PD];
    float4 CCa, CCb;
#pragma unroll
    for (int j = 0; j < PD; ++j) REFILL(j);
    CCa = pf4[0];
    CCb = pf4[CHUNKS];

    float s;
    if (warm_w == 0) {
        s = C_DB * __log2f(fabsf(x[row * N_SAMP]) + 1e-8f);  // exact init
    } else {
        // seed: fixed point of all-attack plane, biased 25 dB low
        const float SEST = (float)(1.0 / (1.0 - slope16(16)));
        s = fmaf(CCa.x, SEST, -25.0f);
    }

    // advance pointers to next block (refills during block i load block i+1)
    {
        pf0 += PD * CHUNKS; pf1 += PD * CHUNKS;
        pf2 += PD * CHUNKS; pf3 += PD * CHUNKS;
        pf4 += 2 * CHUNKS;
        fk = PD;
        if (fk == CW) { fk = 0; ++fq; pf0 = b0 + fq; pf1 = b1 + fq;
                        pf2 = b2 + fq; pf3 = b3 + fq; pf4 = b4 + fq; }
    }

    // ---- warmup (no stores) ----
    int nwb = (start_w - warm_w) >> 3;
    for (int i = 0; i < nwb; ++i) BLOCK8();

    // ---- active: CW/PD = 11 blocks, store entry states ----
    float* en = g_entry + row * EPR + start_w;
    for (int i = 0; i < CW / PD; ++i) {
        float ss[PD];
        {
            ss[0] = s; STEP(0, CCa.x); REFILL(0);
            ss[1] = s; STEP(1, CCa.y); REFILL(1);
            ss[2] = s; STEP(2, CCa.z); REFILL(2);
            ss[3] = s; STEP(3, CCa.w); REFILL(3);
            CCa = pf4[0];
            ss[4] = s; STEP(4, CCb.x); REFILL(4);
            ss[5] = s; STEP(5, CCb.y); REFILL(5);
            ss[6] = s; STEP(6, CCb.z); REFILL(6);
            ss[7] = s; STEP(7, CCb.w); REFILL(7);
            CCb = pf4[CHUNKS];
            ADVANCE();
        }
        float4* e4 = (float4*)(en + i * PD);
        e4[0] = make_float4(ss[0], ss[1], ss[2], ss[3]);
        e4[1] = make_float4(ss[4], ss[5], ss[6], ss[7]);
    }
}

// ---------------- kernel 3: expand + LUT epilogue -------------------------
__global__ void __launch_bounds__(256) k_expand(const float* __restrict__ x,
                                                const float* __restrict__ thr,
                                                const float* __restrict__ dep,
                                                float* __restrict__ out) {
    int wi = blockIdx.x * 256 + threadIdx.x;
    if (wi >= WPR16) return;
    int row = blockIdx.y;

    float tdb = fmaf(thr[row], 40.0f, -40.0f);
    float dpv = dep[row];
    bool  d1  = (dpv == 1.0f);
    float off = (-tdb - LUT_LO_F) * LUT_INVSTEP_F;

    const float AT = (float)A_AT_D, RL = (float)A_REL_D;
    const float BT = 1.0f - AT, BR = 1.0f - RL;

    float s = g_entry[row * EPR + wi];

    const float* xr = x + row * N_SAMP;
    float* outr = out + row * N_SAMP;
    int base = wi * 16;
    int nval = (wi < FULLW) ? 16 : (N_SAMP - base);

    float xi[16];
    if (nval == 16) {
        const float4* x4 = (const float4*)(xr + base);
        float4 a = x4[0], b = x4[1], c = x4[2], d = x4[3];
        xi[0]=a.x; xi[1]=a.y; xi[2]=a.z; xi[3]=a.w;
        xi[4]=b.x; xi[5]=b.y; xi[6]=b.z; xi[7]=b.w;
        xi[8]=c.x; xi[9]=c.y; xi[10]=c.z; xi[11]=c.w;
        xi[12]=d.x; xi[13]=d.y; xi[14]=d.z; xi[15]=d.w;
    } else {
#pragma unroll
        for (int i = 0; i < 16; ++i)
            xi[i] = (i < nval) ? xr[base + i] : 0.0f;
    }

    float o[16];
#pragma unroll
    for (int i = 0; i < 16; ++i) {
        float v = C_DB * __log2f(fabsf(xi[i]) + 1e-8f);
        s = fmaxf(fmaf(AT, s, BT * v), fmaf(RL, s, BR * v));

        float fi = fmaf(s, LUT_INVSTEP_F, off);
        fi = fminf(fmaxf(fi, 0.0f), (float)(LUT_N - 2) + 0.999f);
        int   ii = (int)fi;
        float fr = fi - (float)ii;
        float2 e = g_lut[ii];
        float m = fmaf(fr, e.y, e.x);
        if (!d1) m = exp2f(__log2f(m) * dpv);
        o[i] = xi[i] * m;
    }

    if (nval == 16) {
        float4* o4 = (float4*)(outr + base);
        o4[0] = make_float4(o[0],  o[1],  o[2],  o[3]);
        o4[1] = make_float4(o[4],  o[5],  o[6],  o[7]);
        o4[2] = make_float4(o[8],  o[9],  o[10], o[11]);
        o4[3] = make_float4(o[12], o[13], o[14], o[15]);
    } else {
#pragma unroll
        for (int i = 0; i < 16; ++i)
            if (i < nval) outr[base + i] = o[i];
    }
}

// ---------------- entry point ----------------
extern "C" void kernel_launch(void* const* d_in, const int* in_sizes, int n_in,
                              void* d_out, int out_size) {
    const float* x   = (const float*)d_in[0];
    const float* thr = (const float*)d_in[1];
    const float* dep = (const float*)d_in[2];
    float* out = (float*)d_out;

    k_prepass<<<dim3(CW, ROWS), CHUNKS>>>(x);
    k_scan<<<(ROWS * CHUNKS) / 32, 32>>>(x);
    k_expand<<<dim3((WPR16 + 255) / 256, ROWS), 256>>>(x, thr, dep, out);
}